// round 1
// baseline (speedup 1.0000x reference)
#include <cuda_runtime.h>
#include <math.h>

#define Nn 12288
#define Ff 256
#define Hh 64
#define Cc 16
#define MAXDEG 256
#define ALPHAc 0.3f
#define LN_EPS 1e-5f

// ---------------- scratch (static device globals; no runtime allocation) ----------------
__device__ int    g_colidx[Nn * MAXDEG];   // per-row neighbor lists (column-sorted)
__device__ int    g_deg[Nn];               // adjacency row nnz
__device__ float  g_dinv[Nn];              // rsqrt(deg+1)
__device__ float  g_rowsum[Nn];            // W row sums (symmetric => col sums too)
__device__ float  g_h0[Nn * Hh];
__device__ float  g_h [Nn * Hh];
__device__ float  g_agg[Nn * Hh];
__device__ float  g_gm[Nn * Cc];           // g = relu(out)/sqrt(deg)
__device__ double g_acc[3];                // [0]=sum rowsum*s, [1]=sum (Wg).g, [2]=Wsum

// ---------------- init accumulators ----------------
__global__ void k_init() {
    if (threadIdx.x < 3) g_acc[threadIdx.x] = 0.0;
}

// ---------------- build CSR from dense 0/1 adjacency: one warp per row ----------------
__global__ void k_csr(const float* __restrict__ adj) {
    int warp = (blockIdx.x * blockDim.x + threadIdx.x) >> 5;
    if (warp >= Nn) return;
    int lane = threadIdx.x & 31;
    const float4* arow = (const float4*)(adj + (size_t)warp * Nn);
    int cnt = 0;
    int base = warp * MAXDEG;
    #pragma unroll 1
    for (int c0 = 0; c0 < Nn / 4; c0 += 32) {
        float4 v = arow[c0 + lane];
        int n0 = (v.x != 0.f), n1 = (v.y != 0.f), n2 = (v.z != 0.f), n3 = (v.w != 0.f);
        int lc = n0 + n1 + n2 + n3;
        int inc = lc;
        #pragma unroll
        for (int d = 1; d < 32; d <<= 1) {
            int t = __shfl_up_sync(0xffffffffu, inc, d);
            if (lane >= d) inc += t;
        }
        int pos = base + cnt + inc - lc;       // inc-lc = exclusive prefix
        int col = (c0 + lane) * 4;
        if (n0) g_colidx[pos++] = col + 0;
        if (n1) g_colidx[pos++] = col + 1;
        if (n2) g_colidx[pos++] = col + 2;
        if (n3) g_colidx[pos++] = col + 3;
        cnt += __shfl_sync(0xffffffffu, inc, 31);
    }
    if (lane == 0) {
        g_deg[warp]  = cnt;
        g_dinv[warp] = rsqrtf((float)cnt + 1.0f);   // A = adj + I => rowsum = cnt+1
    }
}

// ---------------- W row sums + Wsum: one warp per row ----------------
__global__ void k_rowsum() {
    int row = (blockIdx.x * blockDim.x + threadIdx.x) >> 5;
    if (row >= Nn) return;
    int lane = threadIdx.x & 31;
    int deg = g_deg[row];
    const int* ci = g_colidx + row * MAXDEG;
    float s = 0.f;
    for (int e = lane; e < deg; e += 32) s += g_dinv[ci[e]];
    #pragma unroll
    for (int d = 16; d; d >>= 1) s += __shfl_xor_sync(0xffffffffu, s, d);
    if (lane == 0) {
        float du = g_dinv[row];
        float rs = du * (du + s);     // includes self-loop dinv_u^2
        g_rowsum[row] = rs;
        atomicAdd(&g_acc[2], (double)rs);
    }
}

// ---------------- h0 = x @ W_in + b_in: one warp per row ----------------
__global__ void k_in(const float* __restrict__ x, const float* __restrict__ Win,
                     const float* __restrict__ bin) {
    int row = (blockIdx.x * blockDim.x + threadIdx.x) >> 5;
    if (row >= Nn) return;
    int lane = threadIdx.x & 31;
    const float* xr = x + (size_t)row * Ff;
    float a0 = 0.f, a1 = 0.f;
    for (int k0 = 0; k0 < Ff; k0 += 32) {
        float xv = xr[k0 + lane];
        #pragma unroll
        for (int j = 0; j < 32; j++) {
            float xk = __shfl_sync(0xffffffffu, xv, j);
            const float* w = Win + (size_t)(k0 + j) * Hh;
            a0 = fmaf(xk, w[lane],      a0);
            a1 = fmaf(xk, w[lane + 32], a1);
        }
    }
    a0 += bin[lane]; a1 += bin[lane + 32];
    g_h0[row * Hh + lane]      = a0;
    g_h0[row * Hh + lane + 32] = a1;
    g_h [row * Hh + lane]      = a0;
    g_h [row * Hh + lane + 32] = a1;
}

// ---------------- agg = W @ h  (CSR SpMM, 16 threads per row, float4) ----------------
__global__ void k_spmm() {
    int row = blockIdx.x * 16 + (threadIdx.x >> 4);
    if (row >= Nn) return;
    int j = threadIdx.x & 15;
    const float4* h4 = (const float4*)g_h;
    float du = g_dinv[row];
    float4 hv = h4[row * 16 + j];
    float4 acc;
    acc.x = du * hv.x; acc.y = du * hv.y; acc.z = du * hv.z; acc.w = du * hv.w;
    int deg = g_deg[row];
    const int* ci = g_colidx + row * MAXDEG;
    #pragma unroll 4
    for (int e = 0; e < deg; e++) {
        int v = ci[e];
        float dv = g_dinv[v];
        float4 hx = h4[v * 16 + j];
        acc.x = fmaf(dv, hx.x, acc.x);
        acc.y = fmaf(dv, hx.y, acc.y);
        acc.z = fmaf(dv, hx.z, acc.z);
        acc.w = fmaf(dv, hx.w, acc.w);
    }
    float4 o;
    o.x = du * acc.x; o.y = du * acc.y; o.z = du * acc.z; o.w = du * acc.w;
    ((float4*)g_agg)[row * 16 + j] = o;
}

// ---- h = (1-beta)*hm + beta*(hm@Wc); hm = (1-a)*agg + a*h0; then relu+LN (not last) ----
__global__ void k_layer(const float* __restrict__ Wc, const float* __restrict__ lng,
                        const float* __restrict__ lnb, float beta, int do_ln) {
    __shared__ float sW[Hh * Hh];     // 16 KB
    __shared__ float sHm[8][Hh];
    for (int i = threadIdx.x; i < Hh * Hh; i += blockDim.x) sW[i] = Wc[i];
    __syncthreads();
    int w = threadIdx.x >> 5, lane = threadIdx.x & 31;
    int row = blockIdx.x * 8 + w;
    if (row >= Nn) return;
    float hm0 = fmaf(1.f - ALPHAc, g_agg[row * Hh + lane],      ALPHAc * g_h0[row * Hh + lane]);
    float hm1 = fmaf(1.f - ALPHAc, g_agg[row * Hh + lane + 32], ALPHAc * g_h0[row * Hh + lane + 32]);
    sHm[w][lane] = hm0; sHm[w][lane + 32] = hm1;
    __syncwarp();
    float t0 = 0.f, t1 = 0.f;
    #pragma unroll
    for (int k = 0; k < Hh; k++) {
        float hk = sHm[w][k];
        t0 = fmaf(hk, sW[k * Hh + lane],      t0);
        t1 = fmaf(hk, sW[k * Hh + lane + 32], t1);
    }
    float v0 = fmaf(beta, t0 - hm0, hm0);   // (1-b)*hm + b*t
    float v1 = fmaf(beta, t1 - hm1, hm1);
    if (do_ln) {
        v0 = fmaxf(v0, 0.f); v1 = fmaxf(v1, 0.f);
        float s = v0 + v1;
        #pragma unroll
        for (int d = 16; d; d >>= 1) s += __shfl_xor_sync(0xffffffffu, s, d);
        float mu = s * (1.f / 64.f);
        float d0 = v0 - mu, d1 = v1 - mu;
        float q = d0 * d0 + d1 * d1;
        #pragma unroll
        for (int d = 16; d; d >>= 1) q += __shfl_xor_sync(0xffffffffu, q, d);
        float rstd = rsqrtf(q * (1.f / 64.f) + LN_EPS);
        v0 = fmaf(d0 * rstd, lng[lane],      lnb[lane]);
        v1 = fmaf(d1 * rstd, lng[lane + 32], lnb[lane + 32]);
    }
    g_h[row * Hh + lane]      = v0;
    g_h[row * Hh + lane + 32] = v1;
}

// ---- out = h@W_out + b_out; logp = log_softmax(out); g, s, term1 ----
__global__ void k_out(const float* __restrict__ Wout, const float* __restrict__ bout,
                      float* __restrict__ dout) {
    __shared__ float sW[Hh * Cc];   // 4 KB
    for (int i = threadIdx.x; i < Hh * Cc; i += blockDim.x) sW[i] = Wout[i];
    __syncthreads();
    int half = threadIdx.x >> 4;    // 16 half-warps of 16 threads
    int c = threadIdx.x & 15;
    int row = blockIdx.x * 16 + half;
    if (row >= Nn) return;
    const float* hr = g_h + row * Hh;
    float acc = bout[c];
    #pragma unroll
    for (int k = 0; k < Hh; k++) acc = fmaf(hr[k], sW[k * Cc + c], acc);
    dout[row * Cc + c] = acc;
    // log_softmax over 16 classes (xor offsets < 16 stay inside the half-warp group)
    float m = acc;
    #pragma unroll
    for (int d = 1; d < 16; d <<= 1) m = fmaxf(m, __shfl_xor_sync(0xffffffffu, m, d));
    float ex = expf(acc - m);
    float se = ex;
    #pragma unroll
    for (int d = 1; d < 16; d <<= 1) se += __shfl_xor_sync(0xffffffffu, se, d);
    dout[Nn * Cc + row * Cc + c] = acc - m - logf(se);
    // Dirichlet pieces: g = relu(out)/sqrt(deg_adj + 2), s = sum g^2
    float gv = fmaxf(acc, 0.f) * rsqrtf((float)g_deg[row] + 2.0f);
    g_gm[row * Cc + c] = gv;
    float s = gv * gv;
    #pragma unroll
    for (int d = 1; d < 16; d <<= 1) s += __shfl_xor_sync(0xffffffffu, s, d);
    if (c == 0) atomicAdd(&g_acc[0], (double)(g_rowsum[row] * s));
}

// ---- term2 = sum_u (W@g)_u . g_u  (16 threads per row) ----
__global__ void k_wg() {
    int row = blockIdx.x * 16 + (threadIdx.x >> 4);
    if (row >= Nn) return;
    int c = threadIdx.x & 15;
    float du = g_dinv[row];
    float gv = g_gm[row * Cc + c];
    float acc = du * gv;
    int deg = g_deg[row];
    const int* ci = g_colidx + row * MAXDEG;
    #pragma unroll 4
    for (int e = 0; e < deg; e++) {
        int v = ci[e];
        acc = fmaf(g_dinv[v], g_gm[v * Cc + c], acc);
    }
    float contrib = du * acc * gv;
    #pragma unroll
    for (int d = 1; d < 16; d <<= 1) contrib += __shfl_xor_sync(0xffffffffu, contrib, d);
    if (c == 0) atomicAdd(&g_acc[1], (double)contrib);
}

__global__ void k_fin(float* __restrict__ dout) {
    // de = 0.5*(2*sum(rowsum*s) - 2*sum((Wg).g)) / Wsum   (W symmetric)
    dout[2 * Nn * Cc] = (float)((g_acc[0] - g_acc[1]) / g_acc[2]);
}

// ---------------- launch ----------------
extern "C" void kernel_launch(void* const* d_in, const int* in_sizes, int n_in,
                              void* d_out, int out_size) {
    const float* x    = (const float*)d_in[0];
    const float* adj  = (const float*)d_in[1];
    const float* Win  = (const float*)d_in[2];
    const float* bin  = (const float*)d_in[3];
    const float* Wcv  = (const float*)d_in[4];   // [4,64,64]
    const float* lng  = (const float*)d_in[5];   // [4,64]
    const float* lnb  = (const float*)d_in[6];   // [4,64]
    const float* Wout = (const float*)d_in[7];
    const float* bout = (const float*)d_in[8];
    float* out = (float*)d_out;

    k_init<<<1, 32>>>();
    k_csr<<<Nn / 8, 256>>>(adj);       // 8 warps/block, warp per row
    k_rowsum<<<Nn / 8, 256>>>();
    k_in<<<Nn / 8, 256>>>(x, Win, bin);

    // beta_i = log(0.3/(i+1) + 1)
    const float betas[4] = {0.26236426446749106f, 0.13976194237515863f,
                            0.09531017980432486f, 0.07232066157962608f};
    for (int i = 0; i < 4; i++) {
        k_spmm<<<Nn / 16, 256>>>();
        k_layer<<<Nn / 8, 256>>>(Wcv + i * Hh * Hh, lng + i * Hh, lnb + i * Hh,
                                 betas[i], (i != 3) ? 1 : 0);
    }
    k_out<<<Nn / 16, 256>>>(Wout, bout, out);
    k_wg<<<Nn / 16, 256>>>();
    k_fin<<<1, 1>>>(out);
}

// round 2
// speedup vs baseline: 1.1018x; 1.1018x over previous
#include <cuda_runtime.h>
#include <math.h>

#define Nn 12288
#define Ff 256
#define Hh 64
#define Cc 16
#define MAXDEG 256
#define ALPHAc 0.3f
#define LN_EPS 1e-5f

// ---------------- scratch ----------------
__device__ int    g_colidx[Nn * MAXDEG];
__device__ int    g_deg[Nn];
__device__ float  g_dinv[Nn];
__device__ float  g_rowsum[Nn];
__device__ float  g_h0[Nn * Hh];
__device__ float  g_h [Nn * Hh];
__device__ float  g_hs[Nn * Hh];           // dinv[u] * h[u]  (pre-scaled for SpMM)
__device__ float  g_gm[Nn * Cc];           // g
__device__ float  g_gs[Nn * Cc];           // dinv[u] * g[u]
__device__ double g_acc[3];

__global__ void k_init() {
    if (threadIdx.x < 3) g_acc[threadIdx.x] = 0.0;
}

// ---------------- CSR build: warp per row, ballot compaction ----------------
__global__ void k_csr(const float* __restrict__ adj) {
    int warp = (blockIdx.x * blockDim.x + threadIdx.x) >> 5;
    if (warp >= Nn) return;
    int lane = threadIdx.x & 31;
    unsigned lt = (1u << lane) - 1u;
    const float4* arow = (const float4*)(adj + (size_t)warp * Nn);
    int cnt = 0;
    int base = warp * MAXDEG;
    #pragma unroll 1
    for (int c0 = 0; c0 < Nn / 4; c0 += 32) {
        float4 v = arow[c0 + lane];
        int n0 = (v.x != 0.f), n1 = (v.y != 0.f), n2 = (v.z != 0.f), n3 = (v.w != 0.f);
        unsigned b0 = __ballot_sync(0xffffffffu, n0);
        unsigned b1 = __ballot_sync(0xffffffffu, n1);
        unsigned b2 = __ballot_sync(0xffffffffu, n2);
        unsigned b3 = __ballot_sync(0xffffffffu, n3);
        int col = (c0 + lane) * 4;
        int t0 = __popc(b0), t1 = __popc(b1), t2 = __popc(b2);
        if (n0) g_colidx[base + cnt + __popc(b0 & lt)] = col;
        if (n1) g_colidx[base + cnt + t0 + __popc(b1 & lt)] = col + 1;
        if (n2) g_colidx[base + cnt + t0 + t1 + __popc(b2 & lt)] = col + 2;
        if (n3) g_colidx[base + cnt + t0 + t1 + t2 + __popc(b3 & lt)] = col + 3;
        cnt += t0 + t1 + t2 + __popc(b3);
    }
    if (lane == 0) {
        g_deg[warp]  = cnt;
        g_dinv[warp] = rsqrtf((float)cnt + 1.0f);
    }
}

// ---------------- W row sums + Wsum ----------------
__global__ void k_rowsum() {
    int row = (blockIdx.x * blockDim.x + threadIdx.x) >> 5;
    if (row >= Nn) return;
    int lane = threadIdx.x & 31;
    int deg = g_deg[row];
    const int* ci = g_colidx + row * MAXDEG;
    float s = 0.f;
    for (int e = lane; e < deg; e += 32) s += g_dinv[ci[e]];
    #pragma unroll
    for (int d = 16; d; d >>= 1) s += __shfl_xor_sync(0xffffffffu, s, d);
    if (lane == 0) {
        float du = g_dinv[row];
        float rs = du * (du + s);
        g_rowsum[row] = rs;
        atomicAdd(&g_acc[2], (double)rs);
    }
}

// ---------------- h0 = x @ W_in + b_in: 4 rows per warp (W-load reuse) ----------------
__global__ void k_in(const float* __restrict__ x, const float* __restrict__ Win,
                     const float* __restrict__ bin) {
    int warp = (blockIdx.x * blockDim.x + threadIdx.x) >> 5;
    int r0 = warp * 4;
    if (r0 >= Nn) return;
    int lane = threadIdx.x & 31;
    float a00 = 0.f, a01 = 0.f, a10 = 0.f, a11 = 0.f;
    float a20 = 0.f, a21 = 0.f, a30 = 0.f, a31 = 0.f;
    #pragma unroll 1
    for (int k0 = 0; k0 < Ff; k0 += 32) {
        float xv0 = x[(size_t)(r0 + 0) * Ff + k0 + lane];
        float xv1 = x[(size_t)(r0 + 1) * Ff + k0 + lane];
        float xv2 = x[(size_t)(r0 + 2) * Ff + k0 + lane];
        float xv3 = x[(size_t)(r0 + 3) * Ff + k0 + lane];
        #pragma unroll
        for (int j = 0; j < 32; j++) {
            const float* w = Win + (size_t)(k0 + j) * Hh;
            float w0 = w[lane], w1 = w[lane + 32];
            float xk0 = __shfl_sync(0xffffffffu, xv0, j);
            float xk1 = __shfl_sync(0xffffffffu, xv1, j);
            float xk2 = __shfl_sync(0xffffffffu, xv2, j);
            float xk3 = __shfl_sync(0xffffffffu, xv3, j);
            a00 = fmaf(xk0, w0, a00); a01 = fmaf(xk0, w1, a01);
            a10 = fmaf(xk1, w0, a10); a11 = fmaf(xk1, w1, a11);
            a20 = fmaf(xk2, w0, a20); a21 = fmaf(xk2, w1, a21);
            a30 = fmaf(xk3, w0, a31 * 0.f + a30); a31 = fmaf(xk3, w1, a31);
        }
    }
    float b0 = bin[lane], b1 = bin[lane + 32];
    float va[4][2] = {{a00 + b0, a01 + b1}, {a10 + b0, a11 + b1},
                      {a20 + b0, a21 + b1}, {a30 + b0, a31 + b1}};
    #pragma unroll
    for (int i = 0; i < 4; i++) {
        int row = r0 + i;
        float du = g_dinv[row];
        g_h0[row * Hh + lane]      = va[i][0];
        g_h0[row * Hh + lane + 32] = va[i][1];
        g_h [row * Hh + lane]      = va[i][0];
        g_h [row * Hh + lane + 32] = va[i][1];
        g_hs[row * Hh + lane]      = du * va[i][0];
        g_hs[row * Hh + lane + 32] = du * va[i][1];
    }
}

// ------- fused layer: SpMM gather + residual mix + 64x64 GEMM + ReLU + LN -------
// block = 256 threads = 16 rows x 16 threads; thread covers 4 contiguous cols
__global__ void k_layer_f(const float* __restrict__ Wc, const float* __restrict__ lng,
                          const float* __restrict__ lnb, float beta, int do_ln) {
    __shared__ float sW[Hh * Hh];         // 16 KB, col-major-friendly: sW[k*64 + c]
    __shared__ float sHm[16][Hh + 4];     // padded, row starts 16B-aligned (68*4=272)
    {
        const float4* src = (const float4*)Wc;
        float4* dst = (float4*)sW;
        for (int i = threadIdx.x; i < Hh * Hh / 4; i += 256) dst[i] = src[i];
    }
    int r = threadIdx.x >> 4;
    int j = threadIdx.x & 15;
    int row = blockIdx.x * 16 + r;
    float du = g_dinv[row];
    const float4* hs4 = (const float4*)g_hs;

    // gather: acc = hs_u + sum_{v in N(u)} hs_v   (2 accumulators for ILP)
    float4 acc = hs4[row * 16 + j];
    float4 acc2 = make_float4(0.f, 0.f, 0.f, 0.f);
    int deg = g_deg[row];
    const int* ci = g_colidx + row * MAXDEG;
    int e = 0;
    #pragma unroll 2
    for (; e + 2 <= deg; e += 2) {
        int v0 = ci[e], v1 = ci[e + 1];
        float4 x0 = hs4[v0 * 16 + j];
        float4 x1 = hs4[v1 * 16 + j];
        acc.x += x0.x; acc.y += x0.y; acc.z += x0.z; acc.w += x0.w;
        acc2.x += x1.x; acc2.y += x1.y; acc2.z += x1.z; acc2.w += x1.w;
    }
    if (e < deg) {
        float4 x0 = hs4[ci[e] * 16 + j];
        acc.x += x0.x; acc.y += x0.y; acc.z += x0.z; acc.w += x0.w;
    }
    acc.x += acc2.x; acc.y += acc2.y; acc.z += acc2.z; acc.w += acc2.w;

    // hm = (1-alpha)*du*acc + alpha*h0
    float4 h0v = ((const float4*)g_h0)[row * 16 + j];
    float c1 = (1.f - ALPHAc) * du;
    float4 hm;
    hm.x = fmaf(c1, acc.x, ALPHAc * h0v.x);
    hm.y = fmaf(c1, acc.y, ALPHAc * h0v.y);
    hm.z = fmaf(c1, acc.z, ALPHAc * h0v.z);
    hm.w = fmaf(c1, acc.w, ALPHAc * h0v.w);
    *(float4*)&sHm[r][4 * j] = hm;
    __syncthreads();

    // GEMM: t[c] = sum_k hm[k] * Wc[k][c], c = 4j..4j+3
    float4 t = make_float4(0.f, 0.f, 0.f, 0.f);
    const float* hmrow = sHm[r];
    const float4* sW4 = (const float4*)sW;
    #pragma unroll
    for (int k = 0; k < Hh; k++) {
        float hk = hmrow[k];
        float4 w = sW4[k * 16 + j];
        t.x = fmaf(hk, w.x, t.x);
        t.y = fmaf(hk, w.y, t.y);
        t.z = fmaf(hk, w.z, t.z);
        t.w = fmaf(hk, w.w, t.w);
    }
    float4 v;
    v.x = fmaf(beta, t.x - hm.x, hm.x);
    v.y = fmaf(beta, t.y - hm.y, hm.y);
    v.z = fmaf(beta, t.z - hm.z, hm.z);
    v.w = fmaf(beta, t.w - hm.w, hm.w);

    if (do_ln) {
        v.x = fmaxf(v.x, 0.f); v.y = fmaxf(v.y, 0.f);
        v.z = fmaxf(v.z, 0.f); v.w = fmaxf(v.w, 0.f);
        float s = v.x + v.y + v.z + v.w;
        #pragma unroll
        for (int d = 8; d; d >>= 1) s += __shfl_xor_sync(0xffffffffu, s, d);
        float mu = s * (1.f / 64.f);
        float dx = v.x - mu, dy = v.y - mu, dz = v.z - mu, dw = v.w - mu;
        float q = dx * dx + dy * dy + dz * dz + dw * dw;
        #pragma unroll
        for (int d = 8; d; d >>= 1) q += __shfl_xor_sync(0xffffffffu, q, d);
        float rstd = rsqrtf(q * (1.f / 64.f) + LN_EPS);
        float4 gg = ((const float4*)lng)[j];
        float4 bb = ((const float4*)lnb)[j];
        v.x = fmaf(dx * rstd, gg.x, bb.x);
        v.y = fmaf(dy * rstd, gg.y, bb.y);
        v.z = fmaf(dz * rstd, gg.z, bb.z);
        v.w = fmaf(dw * rstd, gg.w, bb.w);
        float4 vs;
        vs.x = du * v.x; vs.y = du * v.y; vs.z = du * v.z; vs.w = du * v.w;
        ((float4*)g_hs)[row * 16 + j] = vs;
    }
    ((float4*)g_h)[row * 16 + j] = v;
}

// ---- out = h@W_out + b_out; log_softmax; g, gs, s, term1 ----
__global__ void k_out(const float* __restrict__ Wout, const float* __restrict__ bout,
                      float* __restrict__ dout) {
    __shared__ float sW[Hh * Cc];
    for (int i = threadIdx.x; i < Hh * Cc; i += blockDim.x) sW[i] = Wout[i];
    __syncthreads();
    int half = threadIdx.x >> 4;
    int c = threadIdx.x & 15;
    int row = blockIdx.x * 16 + half;
    const float* hr = g_h + row * Hh;
    float acc = bout[c];
    #pragma unroll
    for (int k = 0; k < Hh; k++) acc = fmaf(hr[k], sW[k * Cc + c], acc);
    dout[row * Cc + c] = acc;
    float m = acc;
    #pragma unroll
    for (int d = 1; d < 16; d <<= 1) m = fmaxf(m, __shfl_xor_sync(0xffffffffu, m, d));
    float ex = expf(acc - m);
    float se = ex;
    #pragma unroll
    for (int d = 1; d < 16; d <<= 1) se += __shfl_xor_sync(0xffffffffu, se, d);
    dout[Nn * Cc + row * Cc + c] = acc - m - logf(se);
    float gv = fmaxf(acc, 0.f) * rsqrtf((float)g_deg[row] + 2.0f);
    float du = g_dinv[row];
    g_gm[row * Cc + c] = gv;
    g_gs[row * Cc + c] = du * gv;
    float s = gv * gv;
    #pragma unroll
    for (int d = 1; d < 16; d <<= 1) s += __shfl_xor_sync(0xffffffffu, s, d);
    if (c == 0) atomicAdd(&g_acc[0], (double)(g_rowsum[row] * s));
}

// ---- term2 = sum_u (W@g)_u . g_u   (4 threads/row, float4) ----
__global__ void k_wg() {
    int row = blockIdx.x * 64 + (threadIdx.x >> 2);
    int q = threadIdx.x & 3;
    const float4* gs4 = (const float4*)g_gs;
    float4 acc = gs4[row * 4 + q];
    int deg = g_deg[row];
    const int* ci = g_colidx + row * MAXDEG;
    int e = 0;
    float4 acc2 = make_float4(0.f, 0.f, 0.f, 0.f);
    #pragma unroll 2
    for (; e + 2 <= deg; e += 2) {
        float4 x0 = gs4[ci[e] * 4 + q];
        float4 x1 = gs4[ci[e + 1] * 4 + q];
        acc.x += x0.x; acc.y += x0.y; acc.z += x0.z; acc.w += x0.w;
        acc2.x += x1.x; acc2.y += x1.y; acc2.z += x1.z; acc2.w += x1.w;
    }
    if (e < deg) {
        float4 x0 = gs4[ci[e] * 4 + q];
        acc.x += x0.x; acc.y += x0.y; acc.z += x0.z; acc.w += x0.w;
    }
    acc.x += acc2.x; acc.y += acc2.y; acc.z += acc2.z; acc.w += acc2.w;
    float4 gu = ((const float4*)g_gm)[row * 4 + q];
    float dot = acc.x * gu.x + acc.y * gu.y + acc.z * gu.z + acc.w * gu.w;
    dot += __shfl_xor_sync(0xffffffffu, dot, 1);
    dot += __shfl_xor_sync(0xffffffffu, dot, 2);
    if (q == 0) atomicAdd(&g_acc[1], (double)(g_dinv[row] * dot));
}

__global__ void k_fin(float* __restrict__ dout) {
    dout[2 * Nn * Cc] = (float)((g_acc[0] - g_acc[1]) / g_acc[2]);
}

// ---------------- launch ----------------
extern "C" void kernel_launch(void* const* d_in, const int* in_sizes, int n_in,
                              void* d_out, int out_size) {
    const float* x    = (const float*)d_in[0];
    const float* adj  = (const float*)d_in[1];
    const float* Win  = (const float*)d_in[2];
    const float* bin  = (const float*)d_in[3];
    const float* Wcv  = (const float*)d_in[4];
    const float* lng  = (const float*)d_in[5];
    const float* lnb  = (const float*)d_in[6];
    const float* Wout = (const float*)d_in[7];
    const float* bout = (const float*)d_in[8];
    float* out = (float*)d_out;

    k_init<<<1, 32>>>();
    k_csr<<<Nn / 8, 256>>>(adj);
    k_rowsum<<<Nn / 8, 256>>>();
    k_in<<<Nn / 32, 256>>>(x, Win, bin);     // 8 warps/block, 4 rows/warp

    const float betas[4] = {0.26236426446749106f, 0.13976194237515863f,
                            0.09531017980432486f, 0.07232066157962608f};
    for (int i = 0; i < 4; i++) {
        k_layer_f<<<Nn / 16, 256>>>(Wcv + i * Hh * Hh, lng + i * Hh, lnb + i * Hh,
                                    betas[i], (i != 3) ? 1 : 0);
    }
    k_out<<<Nn / 16, 256>>>(Wout, bout, out);
    k_wg<<<Nn / 64, 256>>>();
    k_fin<<<1, 1>>>(out);
}

// round 3
// speedup vs baseline: 1.2185x; 1.1059x over previous
#include <cuda_runtime.h>
#include <cuda_fp16.h>
#include <math.h>

#define Nn 12288
#define Ff 256
#define Hh 64
#define Cc 16
#define MAXDEG 256
#define ALPHAc 0.3f
#define LN_EPS 1e-5f

// ---------------- scratch ----------------
__device__ int    g_colidx[Nn * MAXDEG];
__device__ int    g_deg[Nn];
__device__ float  g_dinv[Nn];
__device__ float  g_rowsum[Nn];
__device__ float  g_h0[Nn * Hh];
__device__ float  g_h [Nn * Hh];
__device__ __half g_hs[Nn * Hh];           // fp16: dinv[u]*h[u], SpMM gather operand
__device__ float  g_gm[Nn * Cc];
__device__ float  g_gs[Nn * Cc];
__device__ double g_acc[3];

__global__ void k_init() {
    if (threadIdx.x < 3) g_acc[threadIdx.x] = 0.0;
}

// ---------------- CSR build: warp per row, ballot compaction ----------------
__global__ void k_csr(const float* __restrict__ adj) {
    int warp = (blockIdx.x * blockDim.x + threadIdx.x) >> 5;
    if (warp >= Nn) return;
    int lane = threadIdx.x & 31;
    unsigned lt = (1u << lane) - 1u;
    const float4* arow = (const float4*)(adj + (size_t)warp * Nn);
    int cnt = 0;
    int base = warp * MAXDEG;
    #pragma unroll 1
    for (int c0 = 0; c0 < Nn / 4; c0 += 32) {
        float4 v = arow[c0 + lane];
        int n0 = (v.x != 0.f), n1 = (v.y != 0.f), n2 = (v.z != 0.f), n3 = (v.w != 0.f);
        unsigned b0 = __ballot_sync(0xffffffffu, n0);
        unsigned b1 = __ballot_sync(0xffffffffu, n1);
        unsigned b2 = __ballot_sync(0xffffffffu, n2);
        unsigned b3 = __ballot_sync(0xffffffffu, n3);
        int col = (c0 + lane) * 4;
        int t0 = __popc(b0), t1 = __popc(b1), t2 = __popc(b2);
        if (n0) g_colidx[base + cnt + __popc(b0 & lt)] = col;
        if (n1) g_colidx[base + cnt + t0 + __popc(b1 & lt)] = col + 1;
        if (n2) g_colidx[base + cnt + t0 + t1 + __popc(b2 & lt)] = col + 2;
        if (n3) g_colidx[base + cnt + t0 + t1 + t2 + __popc(b3 & lt)] = col + 3;
        cnt += t0 + t1 + t2 + __popc(b3);
    }
    if (lane == 0) {
        g_deg[warp]  = cnt;
        g_dinv[warp] = rsqrtf((float)cnt + 1.0f);
    }
}

// ---------------- W row sums + Wsum ----------------
__global__ void k_rowsum() {
    int row = (blockIdx.x * blockDim.x + threadIdx.x) >> 5;
    if (row >= Nn) return;
    int lane = threadIdx.x & 31;
    int deg = g_deg[row];
    const int* ci = g_colidx + row * MAXDEG;
    float s = 0.f;
    for (int e = lane; e < deg; e += 32) s += g_dinv[ci[e]];
    #pragma unroll
    for (int d = 16; d; d >>= 1) s += __shfl_xor_sync(0xffffffffu, s, d);
    if (lane == 0) {
        float du = g_dinv[row];
        float rs = du * (du + s);
        g_rowsum[row] = rs;
        atomicAdd(&g_acc[2], (double)rs);
    }
}

// ------- h0 = x @ W_in + b_in: smem-tiled GEMM, 64 rows x 64 cols per block -------
// 256 threads: tx=tid&15 (4 cols), ty=tid>>4 (4 rows); k-chunks of 32
__global__ __launch_bounds__(256) void k_in(const float* __restrict__ x,
                                            const float* __restrict__ Win,
                                            const float* __restrict__ bin) {
    __shared__ float xs[64][36];    // padded: stride 36 (16B-aligned, bank-rotated)
    __shared__ float Ws[32][64];
    int tid = threadIdx.x;
    int tx = tid & 15, ty = tid >> 4;
    int row0 = blockIdx.x * 64;
    float acc[4][4];
    #pragma unroll
    for (int i = 0; i < 4; i++)
        #pragma unroll
        for (int jj = 0; jj < 4; jj++) acc[i][jj] = 0.f;

    const float* xBase = x + (size_t)row0 * Ff;
    for (int kc = 0; kc < Ff; kc += 32) {
        #pragma unroll
        for (int l = 0; l < 2; l++) {
            int q = tid + l * 256;          // 0..511
            int r = q >> 3, kk = q & 7;
            float4 v = *(const float4*)(xBase + (size_t)r * Ff + kc + kk * 4);
            *(float4*)&xs[r][kk * 4] = v;
        }
        #pragma unroll
        for (int l = 0; l < 2; l++) {
            int q = tid + l * 256;
            int k = q >> 4, c4 = q & 15;
            *(float4*)&Ws[k][c4 * 4] = ((const float4*)(Win + (size_t)(kc + k) * Hh))[c4];
        }
        __syncthreads();
        #pragma unroll
        for (int kk = 0; kk < 32; kk++) {
            float4 b = *(const float4*)&Ws[kk][tx * 4];
            float a0 = xs[ty * 4 + 0][kk];
            float a1 = xs[ty * 4 + 1][kk];
            float a2 = xs[ty * 4 + 2][kk];
            float a3 = xs[ty * 4 + 3][kk];
            acc[0][0] = fmaf(a0, b.x, acc[0][0]); acc[0][1] = fmaf(a0, b.y, acc[0][1]);
            acc[0][2] = fmaf(a0, b.z, acc[0][2]); acc[0][3] = fmaf(a0, b.w, acc[0][3]);
            acc[1][0] = fmaf(a1, b.x, acc[1][0]); acc[1][1] = fmaf(a1, b.y, acc[1][1]);
            acc[1][2] = fmaf(a1, b.z, acc[1][2]); acc[1][3] = fmaf(a1, b.w, acc[1][3]);
            acc[2][0] = fmaf(a2, b.x, acc[2][0]); acc[2][1] = fmaf(a2, b.y, acc[2][1]);
            acc[2][2] = fmaf(a2, b.z, acc[2][2]); acc[2][3] = fmaf(a2, b.w, acc[2][3]);
            acc[3][0] = fmaf(a3, b.x, acc[3][0]); acc[3][1] = fmaf(a3, b.y, acc[3][1]);
            acc[3][2] = fmaf(a3, b.z, acc[3][2]); acc[3][3] = fmaf(a3, b.w, acc[3][3]);
        }
        __syncthreads();
    }
    float4 bb = ((const float4*)bin)[tx];
    uint2* hs2 = (uint2*)g_hs;     // 4 halves per uint2, 16 per row
    #pragma unroll
    for (int i = 0; i < 4; i++) {
        int row = row0 + ty * 4 + i;
        float du = g_dinv[row];
        float4 v;
        v.x = acc[i][0] + bb.x; v.y = acc[i][1] + bb.y;
        v.z = acc[i][2] + bb.z; v.w = acc[i][3] + bb.w;
        ((float4*)g_h0)[row * 16 + tx] = v;
        ((float4*)g_h )[row * 16 + tx] = v;
        __half2 p0 = __floats2half2_rn(du * v.x, du * v.y);
        __half2 p1 = __floats2half2_rn(du * v.z, du * v.w);
        uint2 o;
        o.x = *(unsigned*)&p0; o.y = *(unsigned*)&p1;
        hs2[row * 16 + tx] = o;
    }
}

// ------- fused layer: fp16 SpMM gather + residual mix + 64x64 GEMM + ReLU + LN -------
// 256 threads = 16 rows x 16 threads; thread covers 4 cols (uint2 of halves)
__global__ __launch_bounds__(256) void k_layer_f(const float* __restrict__ Wc,
                                                 const float* __restrict__ lng,
                                                 const float* __restrict__ lnb,
                                                 float beta, int do_ln) {
    __shared__ float sW[Hh * Hh];
    __shared__ float sHm[16][Hh + 4];
    {
        const float4* src = (const float4*)Wc;
        float4* dst = (float4*)sW;
        for (int i = threadIdx.x; i < Hh * Hh / 4; i += 256) dst[i] = src[i];
    }
    int r = threadIdx.x >> 4;
    int j = threadIdx.x & 15;
    int row = blockIdx.x * 16 + r;
    float du = g_dinv[row];
    const uint2* hs2 = (const uint2*)g_hs;

    // gather acc = sum over {row} u N(row) of hs (fp16 -> fp32 accumulate)
    float ax = 0.f, ay = 0.f, az = 0.f, aw = 0.f;
    float bx = 0.f, by = 0.f, bz = 0.f, bw = 0.f;
    {
        uint2 rw = hs2[row * 16 + j];
        __half2 p0 = *(__half2*)&rw.x, p1 = *(__half2*)&rw.y;
        float2 f0 = __half22float2(p0), f1 = __half22float2(p1);
        ax = f0.x; ay = f0.y; az = f1.x; aw = f1.y;
    }
    int deg = g_deg[row];
    const int* ci = g_colidx + row * MAXDEG;
    int e = 0;
    #pragma unroll 2
    for (; e + 2 <= deg; e += 2) {
        uint2 r0 = hs2[ci[e]     * 16 + j];
        uint2 r1 = hs2[ci[e + 1] * 16 + j];
        float2 f00 = __half22float2(*(__half2*)&r0.x);
        float2 f01 = __half22float2(*(__half2*)&r0.y);
        float2 f10 = __half22float2(*(__half2*)&r1.x);
        float2 f11 = __half22float2(*(__half2*)&r1.y);
        ax += f00.x; ay += f00.y; az += f01.x; aw += f01.y;
        bx += f10.x; by += f10.y; bz += f11.x; bw += f11.y;
    }
    if (e < deg) {
        uint2 r0 = hs2[ci[e] * 16 + j];
        float2 f00 = __half22float2(*(__half2*)&r0.x);
        float2 f01 = __half22float2(*(__half2*)&r0.y);
        ax += f00.x; ay += f00.y; az += f01.x; aw += f01.y;
    }
    ax += bx; ay += by; az += bz; aw += bw;

    // hm = (1-alpha)*du*acc + alpha*h0
    float4 h0v = ((const float4*)g_h0)[row * 16 + j];
    float c1 = (1.f - ALPHAc) * du;
    float4 hm;
    hm.x = fmaf(c1, ax, ALPHAc * h0v.x);
    hm.y = fmaf(c1, ay, ALPHAc * h0v.y);
    hm.z = fmaf(c1, az, ALPHAc * h0v.z);
    hm.w = fmaf(c1, aw, ALPHAc * h0v.w);
    *(float4*)&sHm[r][4 * j] = hm;
    __syncthreads();

    // t[c] = sum_k hm[k] * Wc[k][c]
    float4 t = make_float4(0.f, 0.f, 0.f, 0.f);
    const float* hmrow = sHm[r];
    #pragma unroll
    for (int k = 0; k < Hh; k++) {
        float hk = hmrow[k];
        float4 w = *(const float4*)&sW[k * Hh + 4 * j];
        t.x = fmaf(hk, w.x, t.x);
        t.y = fmaf(hk, w.y, t.y);
        t.z = fmaf(hk, w.z, t.z);
        t.w = fmaf(hk, w.w, t.w);
    }
    float4 v;
    v.x = fmaf(beta, t.x - hm.x, hm.x);
    v.y = fmaf(beta, t.y - hm.y, hm.y);
    v.z = fmaf(beta, t.z - hm.z, hm.z);
    v.w = fmaf(beta, t.w - hm.w, hm.w);

    if (do_ln) {
        v.x = fmaxf(v.x, 0.f); v.y = fmaxf(v.y, 0.f);
        v.z = fmaxf(v.z, 0.f); v.w = fmaxf(v.w, 0.f);
        float s = v.x + v.y + v.z + v.w;
        #pragma unroll
        for (int d = 8; d; d >>= 1) s += __shfl_xor_sync(0xffffffffu, s, d);
        float mu = s * (1.f / 64.f);
        float dx = v.x - mu, dy = v.y - mu, dz = v.z - mu, dw = v.w - mu;
        float q = dx * dx + dy * dy + dz * dz + dw * dw;
        #pragma unroll
        for (int d = 8; d; d >>= 1) q += __shfl_xor_sync(0xffffffffu, q, d);
        float rstd = rsqrtf(q * (1.f / 64.f) + LN_EPS);
        float4 gg = ((const float4*)lng)[j];
        float4 bbv = ((const float4*)lnb)[j];
        v.x = fmaf(dx * rstd, gg.x, bbv.x);
        v.y = fmaf(dy * rstd, gg.y, bbv.y);
        v.z = fmaf(dz * rstd, gg.z, bbv.z);
        v.w = fmaf(dw * rstd, gg.w, bbv.w);
        __half2 p0 = __floats2half2_rn(du * v.x, du * v.y);
        __half2 p1 = __floats2half2_rn(du * v.z, du * v.w);
        uint2 o;
        o.x = *(unsigned*)&p0; o.y = *(unsigned*)&p1;
        ((uint2*)g_hs)[row * 16 + j] = o;
    }
    ((float4*)g_h)[row * 16 + j] = v;
}

// ---- out = h@W_out + b_out; log_softmax; g, gs, s, term1 ----
__global__ void k_out(const float* __restrict__ Wout, const float* __restrict__ bout,
                      float* __restrict__ dout) {
    __shared__ float sW[Hh * Cc];
    for (int i = threadIdx.x; i < Hh * Cc; i += blockDim.x) sW[i] = Wout[i];
    __syncthreads();
    int half = threadIdx.x >> 4;
    int c = threadIdx.x & 15;
    int row = blockIdx.x * 16 + half;
    const float* hr = g_h + row * Hh;
    float acc = bout[c];
    #pragma unroll
    for (int k = 0; k < Hh; k++) acc = fmaf(hr[k], sW[k * Cc + c], acc);
    dout[row * Cc + c] = acc;
    float m = acc;
    #pragma unroll
    for (int d = 1; d < 16; d <<= 1) m = fmaxf(m, __shfl_xor_sync(0xffffffffu, m, d));
    float ex = expf(acc - m);
    float se = ex;
    #pragma unroll
    for (int d = 1; d < 16; d <<= 1) se += __shfl_xor_sync(0xffffffffu, se, d);
    dout[Nn * Cc + row * Cc + c] = acc - m - logf(se);
    float gv = fmaxf(acc, 0.f) * rsqrtf((float)g_deg[row] + 2.0f);
    float du = g_dinv[row];
    g_gm[row * Cc + c] = gv;
    g_gs[row * Cc + c] = du * gv;
    float s = gv * gv;
    #pragma unroll
    for (int d = 1; d < 16; d <<= 1) s += __shfl_xor_sync(0xffffffffu, s, d);
    if (c == 0) atomicAdd(&g_acc[0], (double)(g_rowsum[row] * s));
}

// ---- term2 = sum_u (W@g)_u . g_u   (4 threads/row, float4) ----
__global__ void k_wg() {
    int row = blockIdx.x * 64 + (threadIdx.x >> 2);
    int q = threadIdx.x & 3;
    const float4* gs4 = (const float4*)g_gs;
    float4 acc = gs4[row * 4 + q];
    int deg = g_deg[row];
    const int* ci = g_colidx + row * MAXDEG;
    int e = 0;
    float4 acc2 = make_float4(0.f, 0.f, 0.f, 0.f);
    #pragma unroll 2
    for (; e + 2 <= deg; e += 2) {
        float4 x0 = gs4[ci[e] * 4 + q];
        float4 x1 = gs4[ci[e + 1] * 4 + q];
        acc.x += x0.x; acc.y += x0.y; acc.z += x0.z; acc.w += x0.w;
        acc2.x += x1.x; acc2.y += x1.y; acc2.z += x1.z; acc2.w += x1.w;
    }
    if (e < deg) {
        float4 x0 = gs4[ci[e] * 4 + q];
        acc.x += x0.x; acc.y += x0.y; acc.z += x0.z; acc.w += x0.w;
    }
    acc.x += acc2.x; acc.y += acc2.y; acc.z += acc2.z; acc.w += acc2.w;
    float4 gu = ((const float4*)g_gm)[row * 4 + q];
    float dot = acc.x * gu.x + acc.y * gu.y + acc.z * gu.z + acc.w * gu.w;
    dot += __shfl_xor_sync(0xffffffffu, dot, 1);
    dot += __shfl_xor_sync(0xffffffffu, dot, 2);
    if (q == 0) atomicAdd(&g_acc[1], (double)(g_dinv[row] * dot));
}

__global__ void k_fin(float* __restrict__ dout) {
    dout[2 * Nn * Cc] = (float)((g_acc[0] - g_acc[1]) / g_acc[2]);
}

// ---------------- launch ----------------
extern "C" void kernel_launch(void* const* d_in, const int* in_sizes, int n_in,
                              void* d_out, int out_size) {
    const float* x    = (const float*)d_in[0];
    const float* adj  = (const float*)d_in[1];
    const float* Win  = (const float*)d_in[2];
    const float* bin  = (const float*)d_in[3];
    const float* Wcv  = (const float*)d_in[4];
    const float* lng  = (const float*)d_in[5];
    const float* lnb  = (const float*)d_in[6];
    const float* Wout = (const float*)d_in[7];
    const float* bout = (const float*)d_in[8];
    float* out = (float*)d_out;

    k_init<<<1, 32>>>();
    k_csr<<<Nn / 8, 256>>>(adj);
    k_rowsum<<<Nn / 8, 256>>>();
    k_in<<<Nn / 64, 256>>>(x, Win, bin);     // tiled GEMM, needs g_dinv

    const float betas[4] = {0.26236426446749106f, 0.13976194237515863f,
                            0.09531017980432486f, 0.07232066157962608f};
    for (int i = 0; i < 4; i++) {
        k_layer_f<<<Nn / 16, 256>>>(Wcv + i * Hh * Hh, lng + i * Hh, lnb + i * Hh,
                                    betas[i], (i != 3) ? 1 : 0);
    }
    k_out<<<Nn / 16, 256>>>(Wout, bout, out);
    k_wg<<<Nn / 64, 256>>>();
    k_fin<<<1, 1>>>(out);
}

// round 4
// speedup vs baseline: 1.3961x; 1.1457x over previous
#include <cuda_runtime.h>
#include <cuda_fp16.h>
#include <math.h>

#define Nn 12288
#define Ff 256
#define Hh 64
#define Cc 16
#define MAXDEG 256
#define ALPHAc 0.3f
#define LN_EPS 1e-5f

#define GEMM_BLOCKS 384            // 12288 / 32 rows per block
#define CSR_BLOCKS  1536           // 12288 / 8 rows per block

// ---------------- scratch ----------------
__device__ int    g_colidx[Nn * MAXDEG];
__device__ int    g_deg[Nn];
__device__ float  g_dinv[Nn];
__device__ float  g_rowsum[Nn];
__device__ float  g_h0[Nn * Hh];
__device__ float  g_h [Nn * Hh];
__device__ __half g_hs[Nn * Hh];
__device__ float  g_gm[Nn * Cc];
__device__ float  g_gs[Nn * Cc];
__device__ double g_acc[3];

__global__ void k_init() {
    if (threadIdx.x < 3) g_acc[threadIdx.x] = 0.0;
}

// ======= fused front: blocks [0,384) = x@W_in GEMM ; blocks [384,1920) = CSR build =======
__global__ __launch_bounds__(256) void k_front(const float* __restrict__ adj,
                                               const float* __restrict__ x,
                                               const float* __restrict__ Win,
                                               const float* __restrict__ bin) {
    __shared__ float xs[32][33];    // stride 33: conflict-free scalar access
    __shared__ float Ws[32][64];
    int tid = threadIdx.x;

    if (blockIdx.x < GEMM_BLOCKS) {
        // ---- GEMM: 32 rows x 64 cols per block; thread = 2 rows x 4 cols ----
        int tx = tid & 15, ty = tid >> 4;
        int row0 = blockIdx.x * 32;
        float acc[2][4];
        #pragma unroll
        for (int i = 0; i < 2; i++)
            #pragma unroll
            for (int jj = 0; jj < 4; jj++) acc[i][jj] = 0.f;

        const float* xBase = x + (size_t)row0 * Ff;
        int lr = tid >> 3, lk = (tid & 7) * 4;     // xs loader: row, k-offset
        for (int kc = 0; kc < Ff; kc += 32) {
            float4 v = *(const float4*)(xBase + (size_t)lr * Ff + kc + lk);
            xs[lr][lk + 0] = v.x; xs[lr][lk + 1] = v.y;
            xs[lr][lk + 2] = v.z; xs[lr][lk + 3] = v.w;
            #pragma unroll
            for (int l = 0; l < 2; l++) {
                int q = tid + l * 256;
                int k = q >> 4, c4 = q & 15;
                *(float4*)&Ws[k][c4 * 4] =
                    ((const float4*)(Win + (size_t)(kc + k) * Hh))[c4];
            }
            __syncthreads();
            #pragma unroll
            for (int kk = 0; kk < 32; kk++) {
                float4 b = *(const float4*)&Ws[kk][tx * 4];
                float a0 = xs[ty * 2 + 0][kk];
                float a1 = xs[ty * 2 + 1][kk];
                acc[0][0] = fmaf(a0, b.x, acc[0][0]); acc[0][1] = fmaf(a0, b.y, acc[0][1]);
                acc[0][2] = fmaf(a0, b.z, acc[0][2]); acc[0][3] = fmaf(a0, b.w, acc[0][3]);
                acc[1][0] = fmaf(a1, b.x, acc[1][0]); acc[1][1] = fmaf(a1, b.y, acc[1][1]);
                acc[1][2] = fmaf(a1, b.z, acc[1][2]); acc[1][3] = fmaf(a1, b.w, acc[1][3]);
            }
            __syncthreads();
        }
        float4 bb = ((const float4*)bin)[tx];
        #pragma unroll
        for (int i = 0; i < 2; i++) {
            int row = row0 + ty * 2 + i;
            float4 v;
            v.x = acc[i][0] + bb.x; v.y = acc[i][1] + bb.y;
            v.z = acc[i][2] + bb.z; v.w = acc[i][3] + bb.w;
            ((float4*)g_h0)[row * 16 + tx] = v;
        }
    } else {
        // ---- CSR build: warp per row, 2x unrolled streaming, ballot compaction ----
        int warp = (blockIdx.x - GEMM_BLOCKS) * 8 + (tid >> 5);
        int lane = tid & 31;
        unsigned lt = (1u << lane) - 1u;
        const float4* arow = (const float4*)(adj + (size_t)warp * Nn);
        int cnt = 0;
        int base = warp * MAXDEG;
        #pragma unroll 1
        for (int c0 = 0; c0 < Nn / 4; c0 += 64) {
            float4 va = arow[c0 + lane];
            float4 vb = arow[c0 + 32 + lane];
            // --- group a ---
            {
                int n0 = (va.x != 0.f), n1 = (va.y != 0.f), n2 = (va.z != 0.f), n3 = (va.w != 0.f);
                unsigned b0 = __ballot_sync(0xffffffffu, n0);
                unsigned b1 = __ballot_sync(0xffffffffu, n1);
                unsigned b2 = __ballot_sync(0xffffffffu, n2);
                unsigned b3 = __ballot_sync(0xffffffffu, n3);
                int col = (c0 + lane) * 4;
                int t0 = __popc(b0), t1 = __popc(b1), t2 = __popc(b2);
                if (n0) g_colidx[base + cnt + __popc(b0 & lt)] = col;
                if (n1) g_colidx[base + cnt + t0 + __popc(b1 & lt)] = col + 1;
                if (n2) g_colidx[base + cnt + t0 + t1 + __popc(b2 & lt)] = col + 2;
                if (n3) g_colidx[base + cnt + t0 + t1 + t2 + __popc(b3 & lt)] = col + 3;
                cnt += t0 + t1 + t2 + __popc(b3);
            }
            // --- group b ---
            {
                int n0 = (vb.x != 0.f), n1 = (vb.y != 0.f), n2 = (vb.z != 0.f), n3 = (vb.w != 0.f);
                unsigned b0 = __ballot_sync(0xffffffffu, n0);
                unsigned b1 = __ballot_sync(0xffffffffu, n1);
                unsigned b2 = __ballot_sync(0xffffffffu, n2);
                unsigned b3 = __ballot_sync(0xffffffffu, n3);
                int col = (c0 + 32 + lane) * 4;
                int t0 = __popc(b0), t1 = __popc(b1), t2 = __popc(b2);
                if (n0) g_colidx[base + cnt + __popc(b0 & lt)] = col;
                if (n1) g_colidx[base + cnt + t0 + __popc(b1 & lt)] = col + 1;
                if (n2) g_colidx[base + cnt + t0 + t1 + __popc(b2 & lt)] = col + 2;
                if (n3) g_colidx[base + cnt + t0 + t1 + t2 + __popc(b3 & lt)] = col + 3;
                cnt += t0 + t1 + t2 + __popc(b3);
            }
        }
        if (lane == 0) {
            g_deg[warp]  = cnt;
            g_dinv[warp] = rsqrtf((float)cnt + 1.0f);
        }
    }
}

// ======= mid: rowsum + Wsum + hs = fp16(dinv*h0)  (one warp per row) =======
__global__ void k_mid() {
    int row = (blockIdx.x * blockDim.x + threadIdx.x) >> 5;
    if (row >= Nn) return;
    int lane = threadIdx.x & 31;
    int deg = g_deg[row];
    const int* ci = g_colidx + row * MAXDEG;
    float s = 0.f;
    for (int e = lane; e < deg; e += 32) s += g_dinv[ci[e]];
    #pragma unroll
    for (int d = 16; d; d >>= 1) s += __shfl_xor_sync(0xffffffffu, s, d);
    float du = g_dinv[row];
    if (lane == 0) {
        float rs = du * (du + s);
        g_rowsum[row] = rs;
        atomicAdd(&g_acc[2], (double)rs);
    }
    float h0a = g_h0[row * Hh + lane];
    float h0b = g_h0[row * Hh + lane + 32];
    g_hs[row * Hh + lane]      = __float2half_rn(du * h0a);
    g_hs[row * Hh + lane + 32] = __float2half_rn(du * h0b);
}

// ======= fused layer: fp16 gather (MLP 4) + residual + 64x64 GEMM + ReLU + LN =======
__global__ __launch_bounds__(256) void k_layer_f(const float* __restrict__ Wc,
                                                 const float* __restrict__ lng,
                                                 const float* __restrict__ lnb,
                                                 float beta, int do_ln) {
    __shared__ float sW[Hh * Hh];
    __shared__ float sHm[16][Hh + 4];
    {
        const float4* src = (const float4*)Wc;
        float4* dst = (float4*)sW;
        for (int i = threadIdx.x; i < Hh * Hh / 4; i += 256) dst[i] = src[i];
    }
    int r = threadIdx.x >> 4;
    int j = threadIdx.x & 15;
    int row = blockIdx.x * 16 + r;
    float du = g_dinv[row];
    const uint2* hs2 = (const uint2*)g_hs;

    float A0x, A0y, A0z, A0w;
    {
        uint2 rw = hs2[row * 16 + j];
        float2 f0 = __half22float2(*(__half2*)&rw.x);
        float2 f1 = __half22float2(*(__half2*)&rw.y);
        A0x = f0.x; A0y = f0.y; A0z = f1.x; A0w = f1.y;
    }
    float A1x = 0.f, A1y = 0.f, A1z = 0.f, A1w = 0.f;
    float A2x = 0.f, A2y = 0.f, A2z = 0.f, A2w = 0.f;
    float A3x = 0.f, A3y = 0.f, A3z = 0.f, A3w = 0.f;
    int deg = g_deg[row];
    const int* ci = g_colidx + row * MAXDEG;
    int e = 0;
    #pragma unroll 1
    for (; e + 4 <= deg; e += 4) {
        uint2 r0 = hs2[ci[e + 0] * 16 + j];
        uint2 r1 = hs2[ci[e + 1] * 16 + j];
        uint2 r2 = hs2[ci[e + 2] * 16 + j];
        uint2 r3 = hs2[ci[e + 3] * 16 + j];
        float2 f;
        f = __half22float2(*(__half2*)&r0.x); A0x += f.x; A0y += f.y;
        f = __half22float2(*(__half2*)&r0.y); A0z += f.x; A0w += f.y;
        f = __half22float2(*(__half2*)&r1.x); A1x += f.x; A1y += f.y;
        f = __half22float2(*(__half2*)&r1.y); A1z += f.x; A1w += f.y;
        f = __half22float2(*(__half2*)&r2.x); A2x += f.x; A2y += f.y;
        f = __half22float2(*(__half2*)&r2.y); A2z += f.x; A2w += f.y;
        f = __half22float2(*(__half2*)&r3.x); A3x += f.x; A3y += f.y;
        f = __half22float2(*(__half2*)&r3.y); A3z += f.x; A3w += f.y;
    }
    for (; e < deg; e++) {
        uint2 r0 = hs2[ci[e] * 16 + j];
        float2 f;
        f = __half22float2(*(__half2*)&r0.x); A0x += f.x; A0y += f.y;
        f = __half22float2(*(__half2*)&r0.y); A0z += f.x; A0w += f.y;
    }
    A0x += A1x + A2x + A3x;
    A0y += A1y + A2y + A3y;
    A0z += A1z + A2z + A3z;
    A0w += A1w + A2w + A3w;

    float4 h0v = ((const float4*)g_h0)[row * 16 + j];
    float c1 = (1.f - ALPHAc) * du;
    float4 hm;
    hm.x = fmaf(c1, A0x, ALPHAc * h0v.x);
    hm.y = fmaf(c1, A0y, ALPHAc * h0v.y);
    hm.z = fmaf(c1, A0z, ALPHAc * h0v.z);
    hm.w = fmaf(c1, A0w, ALPHAc * h0v.w);
    *(float4*)&sHm[r][4 * j] = hm;
    __syncthreads();

    float4 t = make_float4(0.f, 0.f, 0.f, 0.f);
    const float* hmrow = sHm[r];
    #pragma unroll
    for (int k = 0; k < Hh; k++) {
        float hk = hmrow[k];
        float4 w = *(const float4*)&sW[k * Hh + 4 * j];
        t.x = fmaf(hk, w.x, t.x);
        t.y = fmaf(hk, w.y, t.y);
        t.z = fmaf(hk, w.z, t.z);
        t.w = fmaf(hk, w.w, t.w);
    }
    float4 v;
    v.x = fmaf(beta, t.x - hm.x, hm.x);
    v.y = fmaf(beta, t.y - hm.y, hm.y);
    v.z = fmaf(beta, t.z - hm.z, hm.z);
    v.w = fmaf(beta, t.w - hm.w, hm.w);

    if (do_ln) {
        v.x = fmaxf(v.x, 0.f); v.y = fmaxf(v.y, 0.f);
        v.z = fmaxf(v.z, 0.f); v.w = fmaxf(v.w, 0.f);
        float s = v.x + v.y + v.z + v.w;
        #pragma unroll
        for (int d = 8; d; d >>= 1) s += __shfl_xor_sync(0xffffffffu, s, d);
        float mu = s * (1.f / 64.f);
        float dx = v.x - mu, dy = v.y - mu, dz = v.z - mu, dw = v.w - mu;
        float q = dx * dx + dy * dy + dz * dz + dw * dw;
        #pragma unroll
        for (int d = 8; d; d >>= 1) q += __shfl_xor_sync(0xffffffffu, q, d);
        float rstd = rsqrtf(q * (1.f / 64.f) + LN_EPS);
        float4 gg = ((const float4*)lng)[j];
        float4 bbv = ((const float4*)lnb)[j];
        v.x = fmaf(dx * rstd, gg.x, bbv.x);
        v.y = fmaf(dy * rstd, gg.y, bbv.y);
        v.z = fmaf(dz * rstd, gg.z, bbv.z);
        v.w = fmaf(dw * rstd, gg.w, bbv.w);
        __half2 p0 = __floats2half2_rn(du * v.x, du * v.y);
        __half2 p1 = __floats2half2_rn(du * v.z, du * v.w);
        uint2 o;
        o.x = *(unsigned*)&p0; o.y = *(unsigned*)&p1;
        ((uint2*)g_hs)[row * 16 + j] = o;
        // intermediate h is never read -> no g_h store
    } else {
        ((float4*)g_h)[row * 16 + j] = v;   // final layer only
    }
}

// ---- out = h@W_out + b_out; log_softmax; g, gs, s, term1 ----
__global__ void k_out(const float* __restrict__ Wout, const float* __restrict__ bout,
                      float* __restrict__ dout) {
    __shared__ float sW[Hh * Cc];
    for (int i = threadIdx.x; i < Hh * Cc; i += blockDim.x) sW[i] = Wout[i];
    __syncthreads();
    int half = threadIdx.x >> 4;
    int c = threadIdx.x & 15;
    int row = blockIdx.x * 16 + half;
    const float* hr = g_h + row * Hh;
    float acc = bout[c];
    #pragma unroll
    for (int k = 0; k < Hh; k++) acc = fmaf(hr[k], sW[k * Cc + c], acc);
    dout[row * Cc + c] = acc;
    float m = acc;
    #pragma unroll
    for (int d = 1; d < 16; d <<= 1) m = fmaxf(m, __shfl_xor_sync(0xffffffffu, m, d));
    float ex = expf(acc - m);
    float se = ex;
    #pragma unroll
    for (int d = 1; d < 16; d <<= 1) se += __shfl_xor_sync(0xffffffffu, se, d);
    dout[Nn * Cc + row * Cc + c] = acc - m - logf(se);
    float gv = fmaxf(acc, 0.f) * rsqrtf((float)g_deg[row] + 2.0f);
    float du = g_dinv[row];
    g_gm[row * Cc + c] = gv;
    g_gs[row * Cc + c] = du * gv;
    float s = gv * gv;
    #pragma unroll
    for (int d = 1; d < 16; d <<= 1) s += __shfl_xor_sync(0xffffffffu, s, d);
    if (c == 0) atomicAdd(&g_acc[0], (double)(g_rowsum[row] * s));
}

// ---- term2 = sum_u (W@g)_u . g_u   (4 threads/row, float4) ----
__global__ void k_wg() {
    int row = blockIdx.x * 64 + (threadIdx.x >> 2);
    int q = threadIdx.x & 3;
    const float4* gs4 = (const float4*)g_gs;
    float4 acc = gs4[row * 4 + q];
    int deg = g_deg[row];
    const int* ci = g_colidx + row * MAXDEG;
    int e = 0;
    float4 acc2 = make_float4(0.f, 0.f, 0.f, 0.f);
    #pragma unroll 2
    for (; e + 2 <= deg; e += 2) {
        float4 x0 = gs4[ci[e] * 4 + q];
        float4 x1 = gs4[ci[e + 1] * 4 + q];
        acc.x += x0.x; acc.y += x0.y; acc.z += x0.z; acc.w += x0.w;
        acc2.x += x1.x; acc2.y += x1.y; acc2.z += x1.z; acc2.w += x1.w;
    }
    if (e < deg) {
        float4 x0 = gs4[ci[e] * 4 + q];
        acc.x += x0.x; acc.y += x0.y; acc.z += x0.z; acc.w += x0.w;
    }
    acc.x += acc2.x; acc.y += acc2.y; acc.z += acc2.z; acc.w += acc2.w;
    float4 gu = ((const float4*)g_gm)[row * 4 + q];
    float dot = acc.x * gu.x + acc.y * gu.y + acc.z * gu.z + acc.w * gu.w;
    dot += __shfl_xor_sync(0xffffffffu, dot, 1);
    dot += __shfl_xor_sync(0xffffffffu, dot, 2);
    if (q == 0) atomicAdd(&g_acc[1], (double)(g_dinv[row] * dot));
}

__global__ void k_fin(float* __restrict__ dout) {
    dout[2 * Nn * Cc] = (float)((g_acc[0] - g_acc[1]) / g_acc[2]);
}

// ---------------- launch ----------------
extern "C" void kernel_launch(void* const* d_in, const int* in_sizes, int n_in,
                              void* d_out, int out_size) {
    const float* x    = (const float*)d_in[0];
    const float* adj  = (const float*)d_in[1];
    const float* Win  = (const float*)d_in[2];
    const float* bin  = (const float*)d_in[3];
    const float* Wcv  = (const float*)d_in[4];
    const float* lng  = (const float*)d_in[5];
    const float* lnb  = (const float*)d_in[6];
    const float* Wout = (const float*)d_in[7];
    const float* bout = (const float*)d_in[8];
    float* out = (float*)d_out;

    k_init<<<1, 32>>>();
    k_front<<<GEMM_BLOCKS + CSR_BLOCKS, 256>>>(adj, x, Win, bin);
    k_mid<<<Nn / 8, 256>>>();

    const float betas[4] = {0.26236426446749106f, 0.13976194237515863f,
                            0.09531017980432486f, 0.07232066157962608f};
    for (int i = 0; i < 4; i++) {
        k_layer_f<<<Nn / 16, 256>>>(Wcv + i * Hh * Hh, lng + i * Hh, lnb + i * Hh,
                                    betas[i], (i != 3) ? 1 : 0);
    }
    k_out<<<Nn / 16, 256>>>(Wout, bout, out);
    k_wg<<<Nn / 64, 256>>>();
    k_fin<<<1, 1>>>(out);
}